// round 5
// baseline (speedup 1.0000x reference)
#include <cuda_runtime.h>

#define NPTS   32768
#define GRIDSZ 16
#define CDIM   64
#define NVERT  (4 * GRIDSZ * GRIDSZ * GRIDSZ)   // 16384
#define CAP    256
#define SXP    68                                // padded row stride (floats)

__device__ int  g_cnt[NVERT];
__device__ int2 g_list[NVERT * CAP];

__global__ void zero_kernel(float4* __restrict__ out4, int nOut4) {
    int i = blockIdx.x * blockDim.x + threadIdx.x;
    if (i < NVERT) g_cnt[i] = 0;
    if (i < nOut4) out4[i] = make_float4(0.f, 0.f, 0.f, 0.f);
}

__global__ void bin_points_kernel(const int* __restrict__ pidx,
                                  const float* __restrict__ pos)
{
    int p = blockIdx.x * blockDim.x + threadIdx.x;
    if (p >= NPTS) return;

    const int k  = pidx[p];
    const float px = pos[p * 3 + 0] * GRIDSZ - 0.5f;
    const float py = pos[p * 3 + 1] * GRIDSZ - 0.5f;
    const float pz = pos[p * 3 + 2] * GRIDSZ - 0.5f;
    const float fx = floorf(px), fy = floorf(py), fz = floorf(pz);

    float wx[2], wy[2], wz[2];
    wx[1] = px - fx; wx[0] = 1.0f - wx[1];
    wy[1] = py - fy; wy[0] = 1.0f - wy[1];
    wz[1] = pz - fz; wz[0] = 1.0f - wz[1];

    int ix[2], iy[2], iz[2];
    ix[0] = min(max((int)fx,     0), GRIDSZ - 1);
    ix[1] = min(max((int)fx + 1, 0), GRIDSZ - 1);
    iy[0] = min(max((int)fy,     0), GRIDSZ - 1);
    iy[1] = min(max((int)fy + 1, 0), GRIDSZ - 1);
    iz[0] = min(max((int)fz,     0), GRIDSZ - 1);
    iz[1] = min(max((int)fz + 1, 0), GRIDSZ - 1);

    #pragma unroll
    for (int cz = 0; cz < 2; ++cz)
        #pragma unroll
        for (int cy = 0; cy < 2; ++cy)
            #pragma unroll
            for (int cx = 0; cx < 2; ++cx) {
                const float w = wz[cz] * wy[cy] * wx[cx];
                const int v = ((k * GRIDSZ + iz[cz]) * GRIDSZ + iy[cy]) * GRIDSZ + ix[cx];
                int slot = atomicAdd(&g_cnt[v], 1);
                if (slot < CAP)
                    g_list[v * CAP + slot] = make_int2(p, __float_as_int(w));
            }
}

// ---------- tf32 helpers ----------
__device__ __forceinline__ unsigned f2tf32(float x) {
    unsigned r; asm("cvt.rna.tf32.f32 %0, %1;" : "=r"(r) : "f"(x)); return r;
}

__device__ __forceinline__ void mma_tf32(float4& d,
                                         unsigned a0, unsigned a1, unsigned a2, unsigned a3,
                                         unsigned b0, unsigned b1)
{
    asm("mma.sync.aligned.m16n8k8.row.col.f32.tf32.tf32.f32 "
        "{%0,%1,%2,%3}, {%4,%5,%6,%7}, {%8,%9}, {%0,%1,%2,%3};"
        : "+f"(d.x), "+f"(d.y), "+f"(d.z), "+f"(d.w)
        : "r"(a0), "r"(a1), "r"(a2), "r"(a3), "r"(b0), "r"(b1));
}

__device__ __forceinline__ void red_add_v2(float* o, float v0, float v1) {
    asm volatile("red.global.add.v2.f32 [%0], {%1,%2};"
                 :: "l"(o), "f"(v0), "f"(v1) : "memory");
}

#define GTPB 128

__global__ void __launch_bounds__(GTPB) gather_kernel(
    const float* __restrict__ K,     // [NVERT][64][64]
    const float* __restrict__ B,     // [NVERT][64]
    const float* __restrict__ xs,    // [N][64]
    float*       __restrict__ out)   // [N][64]
{
    __shared__ unsigned sMh[CDIM][SXP];   // tf32-hi of K[c][f]
    __shared__ unsigned sMl[CDIM][SXP];   // tf32-lo
    __shared__ unsigned sXh[16][SXP];     // tf32-hi of x[point][c]
    __shared__ unsigned sXl[16][SXP];
    __shared__ float    sB[CDIM];
    __shared__ int      sPid[16];
    __shared__ float    sW[16];

    const int v = blockIdx.x;
    int cnt = g_cnt[v];
    if (cnt > CAP) cnt = CAP;
    if (cnt == 0) return;

    const int tid  = threadIdx.x;
    const int wid  = tid >> 5;
    const int lane = tid & 31;
    const int grp  = lane >> 2;      // 0..7
    const int qd   = lane & 3;       // 0..3
    const int n0   = wid * 16;       // this warp's 16 output columns

    // ---- stage matrix (hi/lo) + bias ----
    {
        const float4* Kf4 = reinterpret_cast<const float4*>(K + (size_t)v * CDIM * CDIM);
        #pragma unroll
        for (int j = 0; j < 8; ++j) {
            const int i = tid + j * GTPB;          // float4 index 0..1023
            const float4 m = Kf4[i];
            const int c = i >> 4, col = (i & 15) * 4;
            float e[4] = {m.x, m.y, m.z, m.w};
            #pragma unroll
            for (int t = 0; t < 4; ++t) {
                const unsigned hi = f2tf32(e[t]);
                sMh[c][col + t] = hi;
                sMl[c][col + t] = f2tf32(e[t] - __uint_as_float(hi));
            }
        }
        if (tid < CDIM) sB[tid] = B[(size_t)v * CDIM + tid];
    }

    for (int base = 0; base < cnt; base += 16) {
        __syncthreads();

        if (tid < 16) {
            const int s = base + tid;
            int pid = 0; float w = 0.0f;
            if (s < cnt) {
                const int2 e = g_list[v * CAP + s];
                pid = e.x; w = __int_as_float(e.y);
            }
            sPid[tid] = pid; sW[tid] = w;
        }
        __syncthreads();

        // stage x (hi/lo); 16 points x 16 quads = 256 float4, 2 per thread
        #pragma unroll
        for (int j = 0; j < 2; ++j) {
            const int i = tid + j * GTPB;
            const int slot = i >> 4, col = (i & 15) * 4;
            const float4 xv =
                reinterpret_cast<const float4*>(xs + (size_t)sPid[slot] * CDIM)[i & 15];
            float e[4] = {xv.x, xv.y, xv.z, xv.w};
            #pragma unroll
            for (int t = 0; t < 4; ++t) {
                const unsigned hi = f2tf32(e[t]);
                sXh[slot][col + t] = hi;
                sXl[slot][col + t] = f2tf32(e[t] - __uint_as_float(hi));
            }
        }
        __syncthreads();

        float4 accA0 = make_float4(0,0,0,0), accB0 = make_float4(0,0,0,0);  // tile n0
        float4 accA1 = make_float4(0,0,0,0), accB1 = make_float4(0,0,0,0);  // tile n0+8

        #pragma unroll
        for (int kt = 0; kt < 8; ++kt) {
            const int k0 = kt * 8;
            // A fragments (shared by both n-tiles)
            const unsigned ah0 = sXh[grp    ][k0 + qd    ];
            const unsigned ah1 = sXh[grp + 8][k0 + qd    ];
            const unsigned ah2 = sXh[grp    ][k0 + qd + 4];
            const unsigned ah3 = sXh[grp + 8][k0 + qd + 4];
            const unsigned al0 = sXl[grp    ][k0 + qd    ];
            const unsigned al1 = sXl[grp + 8][k0 + qd    ];
            const unsigned al2 = sXl[grp    ][k0 + qd + 4];
            const unsigned al3 = sXl[grp + 8][k0 + qd + 4];

            // tile 0 (cols n0..n0+7)
            {
                const unsigned bh0 = sMh[k0 + qd    ][n0 + grp];
                const unsigned bh1 = sMh[k0 + qd + 4][n0 + grp];
                const unsigned bl0 = sMl[k0 + qd    ][n0 + grp];
                const unsigned bl1 = sMl[k0 + qd + 4][n0 + grp];
                mma_tf32(accA0, ah0, ah1, ah2, ah3, bh0, bh1);   // hi*Mh
                mma_tf32(accB0, al0, al1, al2, al3, bh0, bh1);   // lo*Mh
                mma_tf32(accB0, ah0, ah1, ah2, ah3, bl0, bl1);   // hi*Ml
            }
            // tile 1 (cols n0+8..n0+15)
            {
                const unsigned bh0 = sMh[k0 + qd    ][n0 + 8 + grp];
                const unsigned bh1 = sMh[k0 + qd + 4][n0 + 8 + grp];
                const unsigned bl0 = sMl[k0 + qd    ][n0 + 8 + grp];
                const unsigned bl1 = sMl[k0 + qd + 4][n0 + 8 + grp];
                mma_tf32(accA1, ah0, ah1, ah2, ah3, bh0, bh1);
                mma_tf32(accB1, al0, al1, al2, al3, bh0, bh1);
                mma_tf32(accB1, ah0, ah1, ah2, ah3, bl0, bl1);
            }
        }

        // ---- epilogue: out[pid][n] += w * (acc + bias) ----
        const int r0 = grp, r1 = grp + 8;
        const int c0 = n0 + 2 * qd;          // tile0 col pair
        const int c1 = n0 + 8 + 2 * qd;      // tile1 col pair

        if (base + r0 < cnt) {
            const float w = sW[r0];
            float* o = out + (size_t)sPid[r0] * CDIM;
            red_add_v2(o + c0, w * (accA0.x + accB0.x + sB[c0]),
                               w * (accA0.y + accB0.y + sB[c0 + 1]));
            red_add_v2(o + c1, w * (accA1.x + accB1.x + sB[c1]),
                               w * (accA1.y + accB1.y + sB[c1 + 1]));
        }
        if (base + r1 < cnt) {
            const float w = sW[r1];
            float* o = out + (size_t)sPid[r1] * CDIM;
            red_add_v2(o + c0, w * (accA0.z + accB0.z + sB[c0]),
                               w * (accA0.w + accB0.w + sB[c0 + 1]));
            red_add_v2(o + c1, w * (accA1.z + accB1.z + sB[c1]),
                               w * (accA1.w + accB1.w + sB[c1 + 1]));
        }
    }
}

extern "C" void kernel_launch(void* const* d_in, const int* in_sizes, int n_in,
                              void* d_out, int out_size)
{
    const int*   pidx = (const int*)  d_in[0];
    const float* pos  = (const float*)d_in[1];
    const float* xs   = (const float*)d_in[2];
    const float* K    = (const float*)d_in[3];
    const float* B    = (const float*)d_in[4];
    float*       out  = (float*)d_out;

    const int nOut4 = out_size / 4;
    const int zN    = (nOut4 > NVERT ? nOut4 : NVERT);
    zero_kernel<<<(zN + 255) / 256, 256>>>((float4*)d_out, nOut4);
    bin_points_kernel<<<(NPTS + 127) / 128, 128>>>(pidx, pos);
    gather_kernel<<<NVERT, GTPB>>>(K, B, xs, out);
}